// round 13
// baseline (speedup 1.0000x reference)
#include <cuda_runtime.h>

// Fixed shapes
#define BB 64
#define LL 512
#define HH 768
#define WW 255
#define H4 (HH / 4)        // 192 float4 per H row
#define WPBLK 16           // words per block
#define BLKPB 16           // blocks per batch
#define GRID (BB * BLKPB)  // 1024 blocks, single wave

// Fused kernel: warp-redundant scan (no smem, no barriers) + gather/mean-pool.
__global__ __launch_bounds__(192, 8) void wordrep_fused_kernel(
        const float4* __restrict__ seq,   // (B, L, H) as float4
        const int*    __restrict__ wl,    // (B, W)
        float4*       __restrict__ out)   // [cls B*H4][ctx B*W*H4]
{
    const int blk  = blockIdx.x;
    const int b    = blk >> 4;            // batch
    const int j    = blk & 15;            // word-group within batch
    const int t    = threadIdx.x;         // float4 column 0..191
    const int lane = t & 31;
    const int w0   = j * WPBLK;           // first word of this block (<= 240)

    const int* wlb = wl + b * WW;

    // ---- per-warp redundant scan: base = 1 + sum(wl[b,0..w0)) ----
    int psum = 0;
    for (int i = lane; i < w0; i += 32)               // <= 8 independent loads
        psum += __ldg(&wlb[i]);
    #pragma unroll
    for (int o = 16; o > 0; o >>= 1)
        psum += __shfl_down_sync(0xffffffffu, psum, o);
    const int base = 1 + __shfl_sync(0xffffffffu, psum, 0);

    // ---- 16-word inclusive scan in lanes 0..15 -> packed meta per lane ----
    const int wi  = w0 + lane;
    const int len = (lane < WPBLK && wi < WW) ? __ldg(&wlb[wi]) : 0;
    int inc = len;
    #pragma unroll
    for (int o = 1; o < 16; o <<= 1) {
        int n = __shfl_up_sync(0xffffffffu, inc, o);
        if (lane >= o) inc += n;
    }
    // start = base + inclusive - len ; pack start | (len<<16)
    const int meta = ((base + inc - len) & 0xffff) | (len << 16);

    // ---- gather/mean-pool 4 chunks of 4 words; meta via 1 shfl per word ----
    const float4* rowb = seq + (size_t)b * LL * H4 + t;
    float4* obase = out + (size_t)BB * H4 + ((size_t)b * WW + w0) * H4 + t;

    #pragma unroll
    for (int cc = 0; cc < 4; cc++) {
        int st[4], ln[4];
        #pragma unroll
        for (int w = 0; w < 4; w++) {
            const int mm = __shfl_sync(0xffffffffu, meta, cc * 4 + w);
            st[w] = mm & 0xffff;
            ln[w] = mm >> 16;
        }

        float4 a[4], a2[4];
        #pragma unroll
        for (int w = 0; w < 4; w++)
            a[w] = __ldg(rowb + st[w] * H4);
        #pragma unroll
        for (int w = 0; w < 4; w++)
            if (ln[w] > 1)
                a2[w] = __ldg(rowb + (st[w] + 1) * H4);

        #pragma unroll
        for (int w = 0; w < 4; w++) {
            const int gw = w0 + cc * 4 + w;
            if (gw >= WW) continue;                   // pad word (only gw==255)
            float4 r;
            if (ln[w] > 0) {
                r = a[w];
                if (ln[w] > 1) {
                    r.x += a2[w].x; r.y += a2[w].y;
                    r.z += a2[w].z; r.w += a2[w].w;
                }
                const float inv = 1.0f / (float)ln[w];    // exact for 1,2
                r.x *= inv; r.y *= inv; r.z *= inv; r.w *= inv;
            } else {
                r = make_float4(0.f, 0.f, 0.f, 0.f);
            }
            __stcs(&obase[((size_t)(cc * 4 + w)) * H4], r);
        }
    }

    // ---- cls row: block 15 of each batch ----
    if (j == BLKPB - 1)
        __stcs(&out[(size_t)b * H4 + t], __ldg(&seq[(size_t)b * LL * H4 + t]));
}

extern "C" void kernel_launch(void* const* d_in, const int* in_sizes, int n_in,
                              void* d_out, int out_size) {
    (void)in_sizes; (void)n_in; (void)out_size;
    const float4* seq = (const float4*)d_in[0];
    const int*    wl  = (const int*)d_in[1];
    float4*       out = (float4*)d_out;

    wordrep_fused_kernel<<<GRID, 192>>>(seq, wl, out);
}

// round 15
// speedup vs baseline: 1.1364x; 1.1364x over previous
#include <cuda_runtime.h>

// Fixed shapes
#define BB 64
#define LL 512
#define HH 768
#define WW 255
#define H4 (HH / 4)        // 192 float4 per H row
#define WPBLK 16           // words per block
#define BLKPB 16           // blocks per batch (16*16=256 >= 255)
#define GRID (BB * BLKPB)  // 1024 blocks, single wave

// One fused kernel: per-block scan (amortized over 16 words) + gather/mean-pool.
__global__ __launch_bounds__(192, 8) void wordrep_fused_kernel(
        const float4* __restrict__ seq,   // (B, L, H) as float4
        const int*    __restrict__ wl,    // (B, W)
        float4*       __restrict__ out)   // [cls B*H4][ctx B*W*H4]
{
    const int blk  = blockIdx.x;
    const int b    = blk >> 4;            // batch
    const int j    = blk & 15;            // word-group within batch
    const int t    = threadIdx.x;         // float4 column 0..191
    const int lane = t & 31;
    const int w0   = j * WPBLK;           // first word of this block (<= 240)

    const int* wlb = wl + b * WW;         // only 4B-aligned: scalar loads ONLY

    __shared__ int s_part[6];
    __shared__ __align__(16) int s_meta[WPBLK];   // start | (len<<16)

    // ---- prefix base = 1 + sum(wl[b, 0..w0)) ; w0 <= 240 < 192*2 ----
    int psum = 0;
    #pragma unroll
    for (int i = t; i < w0; i += 192) psum += __ldg(&wlb[i]);   // <= 2 loads
    psum = __reduce_add_sync(0xffffffffu, psum);    // REDUX.SUM
    if (lane == 0) s_part[t >> 5] = psum;
    __syncthreads();

    // ---- warp 0: 16-word exclusive scan -> packed meta in smem ----
    if (t < 32) {
        int base = 1;
        #pragma unroll
        for (int k = 0; k < 6; k++) base += s_part[k];
        const int wi  = w0 + t;
        const int len = (t < WPBLK && wi < WW) ? __ldg(&wlb[wi]) : 0;
        int ex = len;
        #pragma unroll
        for (int o = 1; o < 16; o <<= 1) {
            int n = __shfl_up_sync(0xffffffffu, ex, o);
            if (lane >= o) ex += n;
        }
        ex -= len;                                    // exclusive
        if (t < WPBLK)
            s_meta[t] = ((base + ex) & 0xffff) | (len << 16);
    }

    // ---- cls row: block j==0 (zero scan prefix -> balances the tail) ----
    if (j == 0)
        __stcs(&out[(size_t)b * H4 + t], __ldg(&seq[(size_t)b * LL * H4 + t]));

    __syncthreads();

    // ---- gather/mean-pool 4 chunks of 4 words ----
    const float4* rowb = seq + (size_t)b * LL * H4 + t;
    float4* obase = out + (size_t)BB * H4 + ((size_t)b * WW + w0) * H4 + t;

    #pragma unroll
    for (int cc = 0; cc < 4; cc++) {
        const int4 m = *(const int4*)&s_meta[cc * 4];   // smem, 16B-aligned
        int st[4], len[4];
        st[0] = m.x & 0xffff; len[0] = m.x >> 16;
        st[1] = m.y & 0xffff; len[1] = m.y >> 16;
        st[2] = m.z & 0xffff; len[2] = m.z >> 16;
        st[3] = m.w & 0xffff; len[3] = m.w >> 16;

        float4 a[4], a2[4];
        #pragma unroll
        for (int w = 0; w < 4; w++)
            a[w] = __ldg(rowb + st[w] * H4);
        #pragma unroll
        for (int w = 0; w < 4; w++)
            if (len[w] > 1)
                a2[w] = __ldg(rowb + (st[w] + 1) * H4);

        #pragma unroll
        for (int w = 0; w < 4; w++) {
            const int gw = w0 + cc * 4 + w;
            if (gw >= WW) continue;                   // pad word (only gw==255)
            float4 r;
            if (len[w] > 0) {
                r = a[w];
                if (len[w] > 1) {
                    r.x += a2[w].x; r.y += a2[w].y;
                    r.z += a2[w].z; r.w += a2[w].w;
                }
                const float inv = 1.0f / (float)len[w];   // exact for 1,2
                r.x *= inv; r.y *= inv; r.z *= inv; r.w *= inv;
            } else {
                r = make_float4(0.f, 0.f, 0.f, 0.f);
            }
            __stcs(&obase[((size_t)(cc * 4 + w)) * H4], r);
        }
    }
}

extern "C" void kernel_launch(void* const* d_in, const int* in_sizes, int n_in,
                              void* d_out, int out_size) {
    (void)in_sizes; (void)n_in; (void)out_size;
    const float4* seq = (const float4*)d_in[0];
    const int*    wl  = (const int*)d_in[1];
    float4*       out = (float4*)d_out;

    wordrep_fused_kernel<<<GRID, 192>>>(seq, wl, out);
}